// round 7
// baseline (speedup 1.0000x reference)
#include <cuda_runtime.h>
#include <cstdint>

#define NHEADS 16
#define OD     1024
#define OF     512        // fp32-exact options [0,512)
#define KD     128
#define NK4    32
#define NTOK   4096
#define EDIM   2048
#define TM     64         // tokens per main block
#define CW     64         // options per chunk per side
#define NIT    8
#define TH     0.032f
#define NEG_INF (-3.402823466e38f)
#define R2CAP  2048

typedef unsigned long long u64;

// ---------------- device scratch ----------------
__device__ __align__(16) float g_wt[(size_t)NHEADS*KD*OF];   // [h][k][o<512] fp32 transposed
__device__ __align__(16) int   g_wq[(size_t)NHEADS*NK4*OF];  // [h][k4][o-512] packed int8
__device__ __align__(16) float g_sw[NHEADS*OF];
__device__ int      g_idx[NTOK*NHEADS];
__device__ unsigned g_r1n;
__device__ uint2    g_r1[NTOK*NHEADS];
__device__ unsigned g_r2n[NHEADS];
__device__ int      g_r2[NHEADS][R2CAP];

// ---------------- smem offsets (bytes) ----------------
#define SM_XS2 0                        // u64 [128][64] x dup  (64KB)
#define SM_XQ  65536                    // int [32][64]         (8KB)
#define SM_WF  73728                    // 2 x f32 [128][64]    (64KB)
#define SM_WQ  139264                   // 2 x int [32][64]     (16KB)
#define SM_SWS 155648                   // 2 x 64 f32
#define SM_SXS 156160                   // 64 f32
#define SM_STG 156416                   // f32 [128][65] staging (33280)
#define SM_TOT 189696

// ---------------- helpers ----------------
#define CP16(dst, src) \
    asm volatile("cp.async.cg.shared.global [%0], [%1], 16;" :: "r"(dst), "l"(src))
#define CPCOMMIT() asm volatile("cp.async.commit_group;" ::: "memory")
#define CPWAIT1()  asm volatile("cp.async.wait_group 1;" ::: "memory")
#define CPWAIT0()  asm volatile("cp.async.wait_group 0;" ::: "memory")

__device__ __forceinline__ uint32_t smem_u32(const void* p) {
    uint32_t a;
    asm("{ .reg .u64 t; cvta.to.shared.u64 t, %1; cvt.u32.u64 %0, t; }" : "=r"(a) : "l"(p));
    return a;
}
__device__ __forceinline__ u64 pack2(float lo, float hi) {
    u64 r; asm("mov.b64 %0, {%1, %2};" : "=l"(r) : "f"(lo), "f"(hi)); return r;
}
__device__ __forceinline__ void unpack2(u64 v, float &lo, float &hi) {
    asm("mov.b64 {%0, %1}, %2;" : "=f"(lo), "=f"(hi) : "l"(v));
}
__device__ __forceinline__ u64 ffma2(u64 a, u64 b, u64 c) {
    u64 d; asm("fma.rn.f32x2 %0, %1, %2, %3;" : "=l"(d) : "l"(a), "l"(b), "l"(c));
    return d;
}
__device__ __forceinline__ int q8(float v, float inv) {
    int a = __float2int_rn(v * inv);
    return a < -127 ? -127 : (a > 127 ? 127 : a);
}
__device__ __forceinline__ void merge3(float& a1, float& a2, float& a3, int& j1, int& j2,
                                       float b1, float b2, float b3, int k1, int k2) {
    if (b1 > a1 || (b1 == a1 && k1 < j1)) {
        float t1 = a1, t2 = a2, t3 = a3; int u1 = j1, u2 = j2;
        a1 = b1; a2 = b2; a3 = b3; j1 = k1; j2 = k2;
        b1 = t1; b2 = t2; b3 = t3; k1 = u1; k2 = u2;
    }
    if (b1 > a2 || (b1 == a2 && k1 < j2)) { a3 = fmaxf(a2, b2); a2 = b1; j2 = k1; }
    else                                  { a3 = fmaxf(a3, b1); }
}

// ---------------- w preprocessing ----------------
// bx<16: options [0,512) -> g_wt fp32 transposed; bx>=16: [512,1024) -> int8 quant
__global__ __launch_bounds__(256) void prep_w_kernel(const float* __restrict__ w) {
    __shared__ __align__(16) float trf[128 * 33];
    if (blockIdx.x == 0 && blockIdx.y == 0) {
        if (threadIdx.x == 0) g_r1n = 0;
        if (threadIdx.x < NHEADS) g_r2n[threadIdx.x] = 0;
    }
    const int h = blockIdx.y, o0 = blockIdx.x * 32;
    const int tid = threadIdx.x, l = tid & 31, wid = tid >> 5;

    if (o0 < OF) {
        for (int r = wid; r < 32; r += 8) {
            float4 v = *(const float4*)(w + ((size_t)h * OD + o0 + r) * KD + l * 4);
            trf[(4*l+0)*33 + r] = v.x; trf[(4*l+1)*33 + r] = v.y;
            trf[(4*l+2)*33 + r] = v.z; trf[(4*l+3)*33 + r] = v.w;
        }
        __syncthreads();
        for (int i = tid; i < 4096; i += 256) {
            int k = i >> 5, rl = i & 31;
            g_wt[((size_t)h * KD + k) * OF + o0 + rl] = trf[k * 33 + rl];
        }
    } else {
        int* tri = (int*)trf;
        __shared__ float sws[32];
        for (int r = wid; r < 32; r += 8) {
            float4 v = *(const float4*)(w + ((size_t)h * OD + o0 + r) * KD + l * 4);
            float mx = fmaxf(fmaxf(fabsf(v.x), fabsf(v.y)), fmaxf(fabsf(v.z), fabsf(v.w)));
#pragma unroll
            for (int off = 16; off; off >>= 1)
                mx = fmaxf(mx, __shfl_xor_sync(0xffffffffu, mx, off));
            float inv = (mx > 0.f) ? 127.f / mx : 0.f;
            int a0 = q8(v.x, inv), a1 = q8(v.y, inv), a2 = q8(v.z, inv), a3 = q8(v.w, inv);
            tri[l * 33 + r] = (a0 & 255) | ((a1 & 255) << 8) | ((a2 & 255) << 16) | ((a3 & 255) << 24);
            if (l == 0) sws[r] = mx * (1.f / 127.f);
        }
        __syncthreads();
        for (int i = tid; i < 1024; i += 256) {
            int k4 = i >> 5, rl = i & 31;
            g_wq[((size_t)h * NK4 + k4) * OF + (o0 - OF) + rl] = tri[k4 * 33 + rl];
        }
        if (tid < 32) g_sw[h * OF + (o0 - OF) + tid] = sws[tid];
    }
}

// ---------------- main hybrid kernel ----------------
// block = 64 tokens x 1 head, 256 threads = 16 tx x 16 ty (4 tokens per ty)
__global__ __launch_bounds__(256) void vq_hybrid_kernel(const float* __restrict__ x) {
    extern __shared__ char sm[];
    const uint32_t sb = smem_u32(sm);
    const int tid = threadIdx.x, l = tid & 31, wrp = tid >> 5;
    const int tx = tid & 15, ty = tid >> 4;
    const int t0 = blockIdx.x * TM, h = blockIdx.y;

    // ---- issue W prefetch for iterations 0,1 ----
    const float* wtsrc = g_wt + (size_t)h * KD * OF;
    const int*   wqsrc = g_wq + (size_t)h * NK4 * OF;
    const float* swsrc = g_sw + (size_t)h * OF;
#pragma unroll
    for (int buf = 0; buf < 2; buf++) {
#pragma unroll
        for (int r = 0; r < 8; r++) {
            int i = tid + 256 * r;
            int k = i >> 4, seg = i & 15;
            CP16(sb + SM_WF + buf * 32768 + (k * 64 + seg * 4) * 4,
                 wtsrc + (size_t)k * OF + buf * CW + seg * 4);
        }
#pragma unroll
        for (int r = 0; r < 2; r++) {
            int i = tid + 256 * r;
            int k4 = i >> 4, seg = i & 15;
            CP16(sb + SM_WQ + buf * 8192 + (k4 * 64 + seg * 4) * 4,
                 wqsrc + (size_t)k4 * OF + buf * CW + seg * 4);
        }
        if (tid < 16)
            CP16(sb + SM_SWS + buf * 256 + tid * 16, swsrc + buf * CW + tid * 4);
        CPCOMMIT();
    }

    // ---- x prologue: load, row-max, quantize, stage, transpose ----
    for (int rr = 0; rr < 8; rr++) {
        int tl = wrp * 8 + rr;
        float4 v = *(const float4*)(x + (size_t)(t0 + tl) * EDIM + h * KD + l * 4);
        float mx = fmaxf(fmaxf(fabsf(v.x), fabsf(v.y)), fmaxf(fabsf(v.z), fabsf(v.w)));
#pragma unroll
        for (int off = 16; off; off >>= 1)
            mx = fmaxf(mx, __shfl_xor_sync(0xffffffffu, mx, off));
        float inv = (mx > 0.f) ? 127.f / mx : 0.f;
        if (l == 0) ((float*)(sm + SM_SXS))[tl] = mx * (1.f / 127.f);
        float* stg = (float*)(sm + SM_STG);
        stg[(4*l+0)*65 + tl] = v.x; stg[(4*l+1)*65 + tl] = v.y;
        stg[(4*l+2)*65 + tl] = v.z; stg[(4*l+3)*65 + tl] = v.w;
        int a0 = q8(v.x, inv), a1 = q8(v.y, inv), a2 = q8(v.z, inv), a3 = q8(v.w, inv);
        ((int*)(sm + SM_XQ))[l * 64 + tl] =
            (a0 & 255) | ((a1 & 255) << 8) | ((a2 & 255) << 16) | ((a3 & 255) << 24);
    }
    __syncthreads();
    {
        const float* stg = (const float*)(sm + SM_STG);
        u64* xs2 = (u64*)(sm + SM_XS2);
        for (int i = tid; i < 8192; i += 256) {
            int k = i >> 6, t = i & 63;
            float f = stg[k * 65 + t];
            xs2[k * 64 + t] = pack2(f, f);
        }
    }

    float fv[4]; int fi[4];
    float v1[4], v2[4], v3[4]; int i1[4], i2[4];
#pragma unroll
    for (int p = 0; p < 4; p++) {
        fv[p] = NEG_INF; fi[p] = 0;
        v1[p] = v2[p] = v3[p] = NEG_INF; i1[p] = 512; i2[p] = 512;
    }

#pragma unroll 1
    for (int it = 0; it < NIT; it++) {
        if (it < NIT - 1) { CPWAIT1(); } else { CPWAIT0(); }
        __syncthreads();
        const int buf = it & 1;

        u64 facc[4][2];
        int iacc[4][4];
#pragma unroll
        for (int p = 0; p < 4; p++) {
            facc[p][0] = 0ULL; facc[p][1] = 0ULL;
#pragma unroll
            for (int u = 0; u < 4; u++) iacc[p][u] = 0;
        }

#pragma unroll 2
        for (int k4 = 0; k4 < NK4; k4++) {
            // int8 side: 4 tokens x 4 options
            int4 xq = *(const int4*)(sm + SM_XQ + k4 * 256 + ty * 16);
            int4 wq = *(const int4*)(sm + SM_WQ + buf * 8192 + k4 * 256 + tx * 16);
            iacc[0][0] = __dp4a(xq.x, wq.x, iacc[0][0]);
            iacc[0][1] = __dp4a(xq.x, wq.y, iacc[0][1]);
            iacc[0][2] = __dp4a(xq.x, wq.z, iacc[0][2]);
            iacc[0][3] = __dp4a(xq.x, wq.w, iacc[0][3]);
            iacc[1][0] = __dp4a(xq.y, wq.x, iacc[1][0]);
            iacc[1][1] = __dp4a(xq.y, wq.y, iacc[1][1]);
            iacc[1][2] = __dp4a(xq.y, wq.z, iacc[1][2]);
            iacc[1][3] = __dp4a(xq.y, wq.w, iacc[1][3]);
            iacc[2][0] = __dp4a(xq.z, wq.x, iacc[2][0]);
            iacc[2][1] = __dp4a(xq.z, wq.y, iacc[2][1]);
            iacc[2][2] = __dp4a(xq.z, wq.z, iacc[2][2]);
            iacc[2][3] = __dp4a(xq.z, wq.w, iacc[2][3]);
            iacc[3][0] = __dp4a(xq.w, wq.x, iacc[3][0]);
            iacc[3][1] = __dp4a(xq.w, wq.y, iacc[3][1]);
            iacc[3][2] = __dp4a(xq.w, wq.z, iacc[3][2]);
            iacc[3][3] = __dp4a(xq.w, wq.w, iacc[3][3]);
            // fp32 side: 4 k-steps, 4 tokens (dup) x 4 options (2 pairs)
#pragma unroll
            for (int j = 0; j < 4; j++) {
                const int k = k4 * 4 + j;
                ulonglong2 xa = *(const ulonglong2*)(sm + SM_XS2 + k * 512 + ty * 32);
                ulonglong2 xb = *(const ulonglong2*)(sm + SM_XS2 + k * 512 + ty * 32 + 16);
                ulonglong2 wp = *(const ulonglong2*)(sm + SM_WF + buf * 32768 + k * 256 + tx * 16);
                facc[0][0] = ffma2(xa.x, wp.x, facc[0][0]);
                facc[0][1] = ffma2(xa.x, wp.y, facc[0][1]);
                facc[1][0] = ffma2(xa.y, wp.x, facc[1][0]);
                facc[1][1] = ffma2(xa.y, wp.y, facc[1][1]);
                facc[2][0] = ffma2(xb.x, wp.x, facc[2][0]);
                facc[2][1] = ffma2(xb.x, wp.y, facc[2][1]);
                facc[3][0] = ffma2(xb.y, wp.x, facc[3][0]);
                facc[3][1] = ffma2(xb.y, wp.y, facc[3][1]);
            }
        }

        // fold fp32 (exact top-1, ascending o, strict >)
        const int obf = it * CW + tx * 4;
#pragma unroll
        for (int p = 0; p < 4; p++) {
            float q0, q1, q2, q3;
            unpack2(facc[p][0], q0, q1);
            unpack2(facc[p][1], q2, q3);
            if (q0 > fv[p]) { fv[p] = q0; fi[p] = obf; }
            if (q1 > fv[p]) { fv[p] = q1; fi[p] = obf + 1; }
            if (q2 > fv[p]) { fv[p] = q2; fi[p] = obf + 2; }
            if (q3 > fv[p]) { fv[p] = q3; fi[p] = obf + 3; }
        }
        // fold int8 (top-3, scaled by sw)
        float4 s = *(const float4*)(sm + SM_SWS + buf * 256 + tx * 16);
        const float sv[4] = { s.x, s.y, s.z, s.w };
        const int obq = OF + it * CW + tx * 4;
#pragma unroll
        for (int p = 0; p < 4; p++) {
            float q[4];
#pragma unroll
            for (int u = 0; u < 4; u++) q[u] = (float)iacc[p][u] * sv[u];
            float m = fmaxf(fmaxf(q[0], q[1]), fmaxf(q[2], q[3]));
            if (m > v3[p]) {
#pragma unroll
                for (int u = 0; u < 4; u++) {
                    float v = q[u]; int o = obq + u;
                    if (v > v1[p]) { v3[p] = v2[p]; v2[p] = v1[p]; i2[p] = i1[p]; v1[p] = v; i1[p] = o; }
                    else if (v > v2[p]) { v3[p] = v2[p]; v2[p] = v; i2[p] = o; }
                    else if (v > v3[p]) { v3[p] = v; }
                }
            }
        }

        __syncthreads();
        if (it < NIT - 2) {
#pragma unroll
            for (int r = 0; r < 8; r++) {
                int i = tid + 256 * r;
                int k = i >> 4, seg = i & 15;
                CP16(sb + SM_WF + buf * 32768 + (k * 64 + seg * 4) * 4,
                     wtsrc + (size_t)k * OF + (it + 2) * CW + seg * 4);
            }
#pragma unroll
            for (int r = 0; r < 2; r++) {
                int i = tid + 256 * r;
                int k4 = i >> 4, seg = i & 15;
                CP16(sb + SM_WQ + buf * 8192 + (k4 * 64 + seg * 4) * 4,
                     wqsrc + (size_t)k4 * OF + (it + 2) * CW + seg * 4);
            }
            if (tid < 16)
                CP16(sb + SM_SWS + buf * 256 + tid * 16, swsrc + (it + 2) * CW + tid * 4);
            CPCOMMIT();
        }
    }

    // ---- reduce across 16 tx lanes (shfl within half-warps) ----
#pragma unroll
    for (int p = 0; p < 4; p++) {
        float a1 = v1[p], a2 = v2[p], a3 = v3[p]; int j1 = i1[p], j2 = i2[p];
        float af = fv[p]; int jf = fi[p];
#pragma unroll
        for (int off = 1; off <= 8; off <<= 1) {
            float b1 = __shfl_xor_sync(0xffffffffu, a1, off);
            float b2 = __shfl_xor_sync(0xffffffffu, a2, off);
            float b3 = __shfl_xor_sync(0xffffffffu, a3, off);
            int   k1 = __shfl_xor_sync(0xffffffffu, j1, off);
            int   k2 = __shfl_xor_sync(0xffffffffu, j2, off);
            merge3(a1, a2, a3, j1, j2, b1, b2, b3, k1, k2);
            float bf = __shfl_xor_sync(0xffffffffu, af, off);
            int   kf = __shfl_xor_sync(0xffffffffu, jf, off);
            if (bf > af || (bf == af && kf < jf)) { af = bf; jf = kf; }
        }
        if (tx == 0) {
            const int t = t0 + ty * 4 + p;
            const float sx = ((const float*)(sm + SM_SXS))[ty * 4 + p];
            float q1 = a1 * sx, q2 = a2 * sx, q3 = a3 * sx;
            int idx = jf;
            if (af >= q1 + TH) {
                // fp32 winner certain
            } else if (q1 - TH > af && (q1 - q2) > TH) {
                idx = j1;
            } else if ((q1 - q3) <= TH) {
                unsigned q = atomicAdd(&g_r2n[h], 1u);
                if (q < R2CAP) g_r2[h][q] = t;
            } else {
                unsigned has2 = ((q1 - q2) <= TH) ? 1u : 0u;
                unsigned qq = atomicAdd(&g_r1n, 1u);
                g_r1[qq] = make_uint2((unsigned)(t * NHEADS + h),
                                      (unsigned)jf | ((unsigned)j1 << 10) |
                                      ((unsigned)j2 << 20) | (has2 << 30));
            }
            g_idx[t * NHEADS + h] = idx;
        }
    }
}

// ---------------- tier-1 rescue: exact fp32 up-to-3-candidate compare ----------------
__global__ __launch_bounds__(256) void rescue1_kernel(const float* __restrict__ x,
                                                      const float* __restrict__ w) {
    const unsigned cnt = g_r1n;
    const int l = threadIdx.x & 31;
    const int gw = (blockIdx.x * 256 + threadIdx.x) >> 5;
    for (unsigned e = gw; e < cnt; e += 2048) {
        uint2 ent = g_r1[e];
        int pair = (int)ent.x, t = pair >> 4, h = pair & 15;
        int c0 = (int)(ent.y & 0x3FF);
        int c1 = (int)((ent.y >> 10) & 0x3FF);
        int c2 = (int)((ent.y >> 20) & 0x3FF);
        bool has2 = (ent.y >> 30) != 0;
        float4 xv = ((const float4*)(x + (size_t)t * EDIM + h * KD))[l];
        float4 w0 = ((const float4*)(w + ((size_t)h * OD + c0) * KD))[l];
        float4 w1 = ((const float4*)(w + ((size_t)h * OD + c1) * KD))[l];
        float4 w2 = ((const float4*)(w + ((size_t)h * OD + c2) * KD))[l];
        float d0 = xv.x * w0.x + xv.y * w0.y + xv.z * w0.z + xv.w * w0.w;
        float d1 = xv.x * w1.x + xv.y * w1.y + xv.z * w1.z + xv.w * w1.w;
        float d2 = xv.x * w2.x + xv.y * w2.y + xv.z * w2.z + xv.w * w2.w;
#pragma unroll
        for (int off = 16; off; off >>= 1) {
            d0 += __shfl_xor_sync(0xffffffffu, d0, off);
            d1 += __shfl_xor_sync(0xffffffffu, d1, off);
            d2 += __shfl_xor_sync(0xffffffffu, d2, off);
        }
        if (l == 0) {
            float bd = d0; int bi = c0;
            if (d1 > bd || (d1 == bd && c1 < bi)) { bd = d1; bi = c1; }
            if (has2 && (d2 > bd || (d2 == bd && c2 < bi))) { bd = d2; bi = c2; }
            g_idx[pair] = bi;
        }
    }
}

// ---------------- tier-2 rescue: batched exact full recompute ----------------
__global__ __launch_bounds__(256) void rescue2_kernel(const float* __restrict__ x,
                                                      const float* __restrict__ w) {
    __shared__ __align__(16) float xs[8][128];
    __shared__ __align__(16) float ws[64][128];
    __shared__ int   toks[8];
    __shared__ float rv[8][2];
    __shared__ int   ri[8][2];

    const int h = blockIdx.x;
    unsigned n = g_r2n[h]; if (n > R2CAP) n = R2CAP;
    const unsigned b0 = blockIdx.y * 8;
    if (b0 >= n) return;
    const int cnt = (int)((n - b0 < 8) ? (n - b0) : 8);
    const int tid = threadIdx.x, ol = tid & 63, tg = tid >> 6;

    if (tid < cnt) toks[tid] = g_r2[h][b0 + tid];
    __syncthreads();
    for (int i = tid; i < cnt * 32; i += 256) {
        int e = i >> 5, k4 = i & 31;
        ((float4*)xs[e])[k4] = ((const float4*)(x + (size_t)toks[e] * EDIM + h * KD))[k4];
    }

    float bv[2] = { NEG_INF, NEG_INF };
    int   bi[2] = { 0, 0 };

    for (int c = 0; c < 16; c++) {
        __syncthreads();
        for (int i = tid; i < 2048; i += 256) {
            int row = i >> 5, k4 = i & 31;
            ((float4*)ws[row])[k4] =
                ((const float4*)(w + ((size_t)h * OD + c * 64 + row) * KD))[k4];
        }
        __syncthreads();
#pragma unroll
        for (int j = 0; j < 2; j++) {
            int e = tg * 2 + j;
            if (e < cnt) {
                float d = 0.f;
#pragma unroll 8
                for (int k4 = 0; k4 < 32; k4++) {
                    int kk = (k4 + ol) & 31;
                    float4 a = ((const float4*)xs[e])[kk];
                    float4 b = ((const float4*)ws[ol])[kk];
                    d += a.x * b.x + a.y * b.y + a.z * b.z + a.w * b.w;
                }
                int o = c * 64 + ol;
                if (d > bv[j]) { bv[j] = d; bi[j] = o; }
            }
        }
    }

#pragma unroll
    for (int j = 0; j < 2; j++) {
        float v = bv[j]; int id = bi[j];
#pragma unroll
        for (int off = 16; off; off >>= 1) {
            float v2 = __shfl_xor_sync(0xffffffffu, v, off);
            int   d2 = __shfl_xor_sync(0xffffffffu, id, off);
            if (v2 > v || (v2 == v && d2 < id)) { v = v2; id = d2; }
        }
        if ((tid & 31) == 0) {
            int e = tg * 2 + j;
            rv[e][(tid >> 5) & 1] = v;
            ri[e][(tid >> 5) & 1] = id;
        }
    }
    __syncthreads();
    if (tid < cnt) {
        float a = rv[tid][0], b = rv[tid][1];
        int ia = ri[tid][0], ib = ri[tid][1];
        int best = (b > a || (b == a && ib < ia)) ? ib : ia;
        g_idx[toks[tid] * NHEADS + h] = best;
    }
}

// ---------------- gather ----------------
__global__ __launch_bounds__(256) void gather_kernel(const float* __restrict__ cb,
                                                     float* __restrict__ out) {
    const float4* cb4 = (const float4*)cb;
    float4* out4 = (float4*)out;
    int q = blockIdx.x * blockDim.x + threadIdx.x;
    int t = q >> 9, r = q & 511;
    int h = r >> 5, j = r & 31;
    int bi = g_idx[t * NHEADS + h];
    out4[(size_t)t * (EDIM / 4) + h * (KD / 4) + j] =
        cb4[((size_t)h * OD + bi) * (KD / 4) + j];
}

extern "C" void kernel_launch(void* const* d_in, const int* in_sizes, int n_in,
                              void* d_out, int out_size) {
    const float* x  = (const float*)d_in[0];
    const float* w  = (const float*)d_in[1];
    const float* cb = (const float*)d_in[2];
    // d_in[3] temperature: mathematically irrelevant in the forward pass.
    float* out = (float*)d_out;

    cudaFuncSetAttribute(vq_hybrid_kernel,
                         cudaFuncAttributeMaxDynamicSharedMemorySize, SM_TOT);

    prep_w_kernel<<<dim3(OD / 32, NHEADS), 256>>>(w);
    vq_hybrid_kernel<<<dim3(NTOK / TM, NHEADS), 256, SM_TOT>>>(x);
    rescue1_kernel<<<256, 256>>>(x, w);
    rescue2_kernel<<<dim3(NHEADS, R2CAP / 8), 256>>>(x, w);
    gather_kernel<<<(NTOK * EDIM / 4) / 256, 256>>>(cb, out);
}

// round 8
// speedup vs baseline: 1.3667x; 1.3667x over previous
#include <cuda_runtime.h>
#include <cstdint>

#define NHEADS 16
#define OD     1024
#define OF     512        // fp32-exact options [0,512)
#define KD     128
#define NK4    32
#define NTOK   4096
#define EDIM   2048
#define TM     64         // tokens per main block
#define CW     64         // options per chunk per side
#define NIT    8
#define TH     0.032f
#define NEG_INF (-3.402823466e38f)
#define R2CAP  2048

typedef unsigned long long u64;

// ---------------- device scratch ----------------
__device__ __align__(16) float g_wt[(size_t)NHEADS*KD*OD];   // [h][k][o] fp32 transposed (ALL options)
__device__ __align__(16) int   g_wq[(size_t)NHEADS*NK4*OF];  // [h][k4][o-512] packed int8
__device__ __align__(16) float g_sw[NHEADS*OF];
__device__ int      g_idx[NTOK*NHEADS];
__device__ unsigned g_r1n;
__device__ uint2    g_r1[NTOK*NHEADS];
__device__ unsigned g_r2n[NHEADS];
__device__ int      g_r2[NHEADS][R2CAP];
__device__ u64      g_best[NTOK*NHEADS];

// ---------------- main-kernel smem offsets (bytes), total 115200 ----------------
#define SM_XS2 0                        // u64 [128][64] x dup        (65536)
#define SM_WF  65536                    // f32 [128][64] w chunk      (32768)
#define SM_WQ  98304                    // int [32][64]  wq chunk     (8192)
#define SM_XQ  106496                   // int [32][64]  xq           (8192)
#define SM_SWS 114688                   // 64 f32
#define SM_SXS 114944                   // 64 f32
#define SM_TOT 115200

// ---------------- helpers ----------------
#define CP16(dst, src) \
    asm volatile("cp.async.cg.shared.global [%0], [%1], 16;" :: "r"(dst), "l"(src))
#define CPCOMMIT() asm volatile("cp.async.commit_group;" ::: "memory")
#define CPWAIT0()  asm volatile("cp.async.wait_group 0;" ::: "memory")

__device__ __forceinline__ uint32_t smem_u32(const void* p) {
    uint32_t a;
    asm("{ .reg .u64 t; cvta.to.shared.u64 t, %1; cvt.u32.u64 %0, t; }" : "=r"(a) : "l"(p));
    return a;
}
__device__ __forceinline__ u64 pack2(float lo, float hi) {
    u64 r; asm("mov.b64 %0, {%1, %2};" : "=l"(r) : "f"(lo), "f"(hi)); return r;
}
__device__ __forceinline__ void unpack2(u64 v, float &lo, float &hi) {
    asm("mov.b64 {%0, %1}, %2;" : "=f"(lo), "=f"(hi) : "l"(v));
}
__device__ __forceinline__ u64 ffma2(u64 a, u64 b, u64 c) {
    u64 d; asm("fma.rn.f32x2 %0, %1, %2, %3;" : "=l"(d) : "l"(a), "l"(b), "l"(c));
    return d;
}
__device__ __forceinline__ int q8(float v, float inv) {
    int a = __float2int_rn(v * inv);
    return a < -127 ? -127 : (a > 127 ? 127 : a);
}
__device__ __forceinline__ void merge3(float& a1, float& a2, float& a3, int& j1, int& j2,
                                       float b1, float b2, float b3, int k1, int k2) {
    if (b1 > a1 || (b1 == a1 && k1 < j1)) {
        float t1 = a1, t2 = a2, t3 = a3; int u1 = j1, u2 = j2;
        a1 = b1; a2 = b2; a3 = b3; j1 = k1; j2 = k2;
        b1 = t1; b2 = t2; b3 = t3; k1 = u1; k2 = u2;
    }
    if (b1 > a2 || (b1 == a2 && k1 < j2)) { a3 = fmaxf(a2, b2); a2 = b1; j2 = k1; }
    else                                  { a3 = fmaxf(a3, b1); }
}
__device__ __forceinline__ unsigned enc_f(float f) {
    unsigned u = __float_as_uint(f);
    return (u & 0x80000000u) ? ~u : (u | 0x80000000u);
}

// ---------------- w preprocessing ----------------
// Every block: 32 options of one head -> g_wt fp32 transposed.
// Blocks with o0 >= 512 additionally produce int8 quantized + scales.
__global__ __launch_bounds__(256) void prep_w_kernel(const float* __restrict__ w) {
    __shared__ float trf[128 * 33];
    __shared__ float sws_s[32], invs[32];
    if (blockIdx.x == 0 && blockIdx.y == 0) {
        if (threadIdx.x == 0) g_r1n = 0;
        if (threadIdx.x < NHEADS) g_r2n[threadIdx.x] = 0;
    }
    const int h = blockIdx.y, o0 = blockIdx.x * 32;
    const int tid = threadIdx.x, l = tid & 31, wid = tid >> 5;

    for (int r = wid; r < 32; r += 8) {
        float4 v = *(const float4*)(w + ((size_t)h * OD + o0 + r) * KD + l * 4);
        trf[(4*l+0)*33 + r] = v.x; trf[(4*l+1)*33 + r] = v.y;
        trf[(4*l+2)*33 + r] = v.z; trf[(4*l+3)*33 + r] = v.w;
        if (o0 >= OF) {
            float mx = fmaxf(fmaxf(fabsf(v.x), fabsf(v.y)), fmaxf(fabsf(v.z), fabsf(v.w)));
#pragma unroll
            for (int off = 16; off; off >>= 1)
                mx = fmaxf(mx, __shfl_xor_sync(0xffffffffu, mx, off));
            if (l == 0) {
                sws_s[r] = mx * (1.f / 127.f);
                invs[r]  = (mx > 0.f) ? 127.f / mx : 0.f;
            }
        }
    }
    __syncthreads();
    for (int i = tid; i < 4096; i += 256) {
        int k = i >> 5, rl = i & 31;
        g_wt[((size_t)h * KD + k) * OD + o0 + rl] = trf[k * 33 + rl];
    }
    if (o0 >= OF) {
        for (int i = tid; i < 1024; i += 256) {
            int k4 = i >> 5, rl = i & 31;
            float inv = invs[rl];
            int a0 = q8(trf[(4*k4+0)*33 + rl], inv);
            int a1 = q8(trf[(4*k4+1)*33 + rl], inv);
            int a2 = q8(trf[(4*k4+2)*33 + rl], inv);
            int a3 = q8(trf[(4*k4+3)*33 + rl], inv);
            g_wq[((size_t)h * NK4 + k4) * OF + (o0 - OF) + rl] =
                (a0 & 255) | ((a1 & 255) << 8) | ((a2 & 255) << 16) | ((a3 & 255) << 24);
        }
        if (tid < 32) g_sw[h * OF + (o0 - OF) + tid] = sws_s[tid];
    }
}

// ---------------- main hybrid kernel (2 blocks/SM) ----------------
__global__ __launch_bounds__(256, 2) void vq_hybrid_kernel(const float* __restrict__ x) {
    extern __shared__ char sm[];
    const uint32_t sb = smem_u32(sm);
    const int tid = threadIdx.x, l = tid & 31, wrp = tid >> 5;
    const int tx = tid & 15, ty = tid >> 4;
    const int t0 = blockIdx.x * TM, h = blockIdx.y;

    const float* wtsrc = g_wt + (size_t)h * KD * OD;
    const int*   wqsrc = g_wq + (size_t)h * NK4 * OF;
    const float* swsrc = g_sw + (size_t)h * OF;

    // ---- prologue: x rows -> dup-packed XS2, int8 XQ, scales ----
    {
        u64* xs2 = (u64*)(sm + SM_XS2);
        int* xq  = (int*)(sm + SM_XQ);
        float* sxs = (float*)(sm + SM_SXS);
#pragma unroll 2
        for (int rr = 0; rr < 8; rr++) {
            int tl = wrp * 8 + rr;
            float4 v = *(const float4*)(x + (size_t)(t0 + tl) * EDIM + h * KD + l * 4);
            float mx = fmaxf(fmaxf(fabsf(v.x), fabsf(v.y)), fmaxf(fabsf(v.z), fabsf(v.w)));
#pragma unroll
            for (int off = 16; off; off >>= 1)
                mx = fmaxf(mx, __shfl_xor_sync(0xffffffffu, mx, off));
            float inv = (mx > 0.f) ? 127.f / mx : 0.f;
            if (l == 0) sxs[tl] = mx * (1.f / 127.f);
            xs2[(4*l+0)*64 + tl] = pack2(v.x, v.x);
            xs2[(4*l+1)*64 + tl] = pack2(v.y, v.y);
            xs2[(4*l+2)*64 + tl] = pack2(v.z, v.z);
            xs2[(4*l+3)*64 + tl] = pack2(v.w, v.w);
            int a0 = q8(v.x, inv), a1 = q8(v.y, inv), a2 = q8(v.z, inv), a3 = q8(v.w, inv);
            xq[l * 64 + tl] = (a0 & 255) | ((a1 & 255) << 8) | ((a2 & 255) << 16) | ((a3 & 255) << 24);
        }
    }

    float fv[4]; int fi[4];
    float v1[4], v2[4], v3[4]; int i1[4], i2[4];
#pragma unroll
    for (int p = 0; p < 4; p++) {
        fv[p] = NEG_INF; fi[p] = 0;
        v1[p] = v2[p] = v3[p] = NEG_INF; i1[p] = OF; i2[p] = OF;
    }

#pragma unroll 1
    for (int it = 0; it < NIT; it++) {
        __syncthreads();   // previous chunk consumed (and prologue visible on it=0)
#pragma unroll
        for (int r = 0; r < 8; r++) {
            int i = tid + 256 * r;
            int k = i >> 4, seg = i & 15;
            CP16(sb + SM_WF + k * 256 + seg * 16,
                 wtsrc + (size_t)k * OD + it * CW + seg * 4);
        }
#pragma unroll
        for (int r = 0; r < 2; r++) {
            int i = tid + 256 * r;
            int k4 = i >> 4, seg = i & 15;
            CP16(sb + SM_WQ + k4 * 256 + seg * 16,
                 wqsrc + (size_t)k4 * OF + it * CW + seg * 4);
        }
        if (tid < 16)
            CP16(sb + SM_SWS + tid * 16, swsrc + it * CW + tid * 4);
        CPCOMMIT(); CPWAIT0();
        __syncthreads();

        u64 facc[4][2];
        int iacc[4][4];
#pragma unroll
        for (int p = 0; p < 4; p++) {
            facc[p][0] = 0ULL; facc[p][1] = 0ULL;
#pragma unroll
            for (int u = 0; u < 4; u++) iacc[p][u] = 0;
        }

#pragma unroll 4
        for (int k4 = 0; k4 < NK4; k4++) {
            int4 xqv = *(const int4*)(sm + SM_XQ + k4 * 256 + ty * 16);
            int4 wqv = *(const int4*)(sm + SM_WQ + k4 * 256 + tx * 16);
            iacc[0][0] = __dp4a(xqv.x, wqv.x, iacc[0][0]);
            iacc[0][1] = __dp4a(xqv.x, wqv.y, iacc[0][1]);
            iacc[0][2] = __dp4a(xqv.x, wqv.z, iacc[0][2]);
            iacc[0][3] = __dp4a(xqv.x, wqv.w, iacc[0][3]);
            iacc[1][0] = __dp4a(xqv.y, wqv.x, iacc[1][0]);
            iacc[1][1] = __dp4a(xqv.y, wqv.y, iacc[1][1]);
            iacc[1][2] = __dp4a(xqv.y, wqv.z, iacc[1][2]);
            iacc[1][3] = __dp4a(xqv.y, wqv.w, iacc[1][3]);
            iacc[2][0] = __dp4a(xqv.z, wqv.x, iacc[2][0]);
            iacc[2][1] = __dp4a(xqv.z, wqv.y, iacc[2][1]);
            iacc[2][2] = __dp4a(xqv.z, wqv.z, iacc[2][2]);
            iacc[2][3] = __dp4a(xqv.z, wqv.w, iacc[2][3]);
            iacc[3][0] = __dp4a(xqv.w, wqv.x, iacc[3][0]);
            iacc[3][1] = __dp4a(xqv.w, wqv.y, iacc[3][1]);
            iacc[3][2] = __dp4a(xqv.w, wqv.z, iacc[3][2]);
            iacc[3][3] = __dp4a(xqv.w, wqv.w, iacc[3][3]);
#pragma unroll
            for (int j = 0; j < 4; j++) {
                const int k = k4 * 4 + j;
                ulonglong2 xa = *(const ulonglong2*)(sm + SM_XS2 + k * 512 + ty * 32);
                ulonglong2 xb = *(const ulonglong2*)(sm + SM_XS2 + k * 512 + ty * 32 + 16);
                ulonglong2 wp = *(const ulonglong2*)(sm + SM_WF + k * 256 + tx * 16);
                facc[0][0] = ffma2(xa.x, wp.x, facc[0][0]);
                facc[0][1] = ffma2(xa.x, wp.y, facc[0][1]);
                facc[1][0] = ffma2(xa.y, wp.x, facc[1][0]);
                facc[1][1] = ffma2(xa.y, wp.y, facc[1][1]);
                facc[2][0] = ffma2(xb.x, wp.x, facc[2][0]);
                facc[2][1] = ffma2(xb.x, wp.y, facc[2][1]);
                facc[3][0] = ffma2(xb.y, wp.x, facc[3][0]);
                facc[3][1] = ffma2(xb.y, wp.y, facc[3][1]);
            }
        }

        // fold fp32 (exact top-1)
        const int obf = it * CW + tx * 4;
#pragma unroll
        for (int p = 0; p < 4; p++) {
            float q0, q1, q2, q3;
            unpack2(facc[p][0], q0, q1);
            unpack2(facc[p][1], q2, q3);
            if (q0 > fv[p]) { fv[p] = q0; fi[p] = obf; }
            if (q1 > fv[p]) { fv[p] = q1; fi[p] = obf + 1; }
            if (q2 > fv[p]) { fv[p] = q2; fi[p] = obf + 2; }
            if (q3 > fv[p]) { fv[p] = q3; fi[p] = obf + 3; }
        }
        // fold int8 (top-3)
        float4 s = *(const float4*)(sm + SM_SWS + tx * 16);
        const float sv[4] = { s.x, s.y, s.z, s.w };
        const int obq = OF + it * CW + tx * 4;
#pragma unroll
        for (int p = 0; p < 4; p++) {
            float q[4];
#pragma unroll
            for (int u = 0; u < 4; u++) q[u] = (float)iacc[p][u] * sv[u];
            float m = fmaxf(fmaxf(q[0], q[1]), fmaxf(q[2], q[3]));
            if (m > v3[p]) {
#pragma unroll
                for (int u = 0; u < 4; u++) {
                    float v = q[u]; int o = obq + u;
                    if (v > v1[p]) { v3[p] = v2[p]; v2[p] = v1[p]; i2[p] = i1[p]; v1[p] = v; i1[p] = o; }
                    else if (v > v2[p]) { v3[p] = v2[p]; v2[p] = v; i2[p] = o; }
                    else if (v > v3[p]) { v3[p] = v; }
                }
            }
        }
    }

    // ---- reduce across 16 tx lanes, decide / flag ----
#pragma unroll
    for (int p = 0; p < 4; p++) {
        float a1 = v1[p], a2 = v2[p], a3 = v3[p]; int j1 = i1[p], j2 = i2[p];
        float af = fv[p]; int jf = fi[p];
#pragma unroll
        for (int off = 1; off <= 8; off <<= 1) {
            float b1 = __shfl_xor_sync(0xffffffffu, a1, off);
            float b2 = __shfl_xor_sync(0xffffffffu, a2, off);
            float b3 = __shfl_xor_sync(0xffffffffu, a3, off);
            int   k1 = __shfl_xor_sync(0xffffffffu, j1, off);
            int   k2 = __shfl_xor_sync(0xffffffffu, j2, off);
            merge3(a1, a2, a3, j1, j2, b1, b2, b3, k1, k2);
            float bf = __shfl_xor_sync(0xffffffffu, af, off);
            int   kf = __shfl_xor_sync(0xffffffffu, jf, off);
            if (bf > af || (bf == af && kf < jf)) { af = bf; jf = kf; }
        }
        if (tx == 0) {
            const int t = t0 + ty * 4 + p;
            const int pair = t * NHEADS + h;
            const float sx = ((const float*)(sm + SM_SXS))[ty * 4 + p];
            float q1 = a1 * sx, q2 = a2 * sx, q3 = a3 * sx;
            const float M = fmaxf(af, q1);
            int idx = jf;
            if (q1 <= af - TH) {
                // fp32 winner certain
            } else if (q3 >= M - TH) {
                unsigned q = atomicAdd(&g_r2n[h], 1u);
                if (q < R2CAP) { g_r2[h][q] = t; g_best[pair] = 0ULL; }
            } else if (af <= q1 - TH && q2 < M - TH) {
                idx = j1;
            } else {
                unsigned has2 = (q2 >= M - TH) ? 1u : 0u;
                unsigned qq = atomicAdd(&g_r1n, 1u);
                g_r1[qq] = make_uint2((unsigned)pair,
                                      (unsigned)jf | ((unsigned)j1 << 10) |
                                      ((unsigned)j2 << 20) | (has2 << 30));
            }
            g_idx[pair] = idx;
        }
    }
}

// ---------------- tier-1 rescue: exact fp32 up-to-3-candidate compare ----------------
__global__ __launch_bounds__(256) void rescue1_kernel(const float* __restrict__ x,
                                                      const float* __restrict__ w) {
    const unsigned cnt = g_r1n;
    const int l = threadIdx.x & 31;
    const int gw = (blockIdx.x * 256 + threadIdx.x) >> 5;
    for (unsigned e = gw; e < cnt; e += 2048) {
        uint2 ent = g_r1[e];
        int pair = (int)ent.x, t = pair >> 4, h = pair & 15;
        int c0 = (int)(ent.y & 0x3FF);
        int c1 = (int)((ent.y >> 10) & 0x3FF);
        int c2 = (int)((ent.y >> 20) & 0x3FF);
        bool has2 = (ent.y >> 30) != 0;
        float4 xv = ((const float4*)(x + (size_t)t * EDIM + h * KD))[l];
        float4 w0 = ((const float4*)(w + ((size_t)h * OD + c0) * KD))[l];
        float4 w1 = ((const float4*)(w + ((size_t)h * OD + c1) * KD))[l];
        float4 w2 = ((const float4*)(w + ((size_t)h * OD + c2) * KD))[l];
        float d0 = xv.x * w0.x + xv.y * w0.y + xv.z * w0.z + xv.w * w0.w;
        float d1 = xv.x * w1.x + xv.y * w1.y + xv.z * w1.z + xv.w * w1.w;
        float d2 = xv.x * w2.x + xv.y * w2.y + xv.z * w2.z + xv.w * w2.w;
#pragma unroll
        for (int off = 16; off; off >>= 1) {
            d0 += __shfl_xor_sync(0xffffffffu, d0, off);
            d1 += __shfl_xor_sync(0xffffffffu, d1, off);
            d2 += __shfl_xor_sync(0xffffffffu, d2, off);
        }
        if (l == 0) {
            float bd = d0; int bi = c0;
            if (d1 > bd || (d1 == bd && c1 < bi)) { bd = d1; bi = c1; }
            if (has2 && (d2 > bd || (d2 == bd && c2 < bi))) { bd = d2; bi = c2; }
            g_idx[pair] = bi;
        }
    }
}

// ---------------- tier-2 rescue: exact full recompute via atomicMax keys ----------------
// block = (head, option-chunk of 128, token-slab of 32). w read coalesced from L2 (g_wt).
__global__ __launch_bounds__(256) void rescue2_kernel(const float* __restrict__ x) {
    __shared__ __align__(16) float xs[128][36];   // [k][token] transposed
    __shared__ int toks[32];
    const int h = blockIdx.x, c = blockIdx.y, slab = blockIdx.z;
    unsigned n = g_r2n[h]; if (n > R2CAP) n = R2CAP;
    const int e0 = slab * 32;
    if (e0 >= (int)n) return;
    const int cnt = ((int)n - e0 < 32) ? ((int)n - e0) : 32;
    const int tid = threadIdx.x;

    if (tid < cnt) toks[tid] = g_r2[h][e0 + tid];
    __syncthreads();
    for (int i = tid; i < cnt * 32; i += 256) {
        int e = i >> 5, k4 = i & 31;
        float4 v = ((const float4*)(x + (size_t)toks[e] * EDIM + h * KD))[k4];
        xs[k4*4+0][e] = v.x; xs[k4*4+1][e] = v.y;
        xs[k4*4+2][e] = v.z; xs[k4*4+3][e] = v.w;
    }
    __syncthreads();

    const int ol = tid & 127, tg = tid >> 7;
    const int o = c * 128 + ol;
    const float* wcol = g_wt + (size_t)h * KD * OD + o;

    float acc[16];
#pragma unroll
    for (int u = 0; u < 16; u++) acc[u] = 0.f;

#pragma unroll 4
    for (int k = 0; k < KD; k++) {
        float wv = wcol[(size_t)k * OD];
        float4 x0 = *(const float4*)&xs[k][tg * 16];
        float4 x1 = *(const float4*)&xs[k][tg * 16 + 4];
        float4 x2 = *(const float4*)&xs[k][tg * 16 + 8];
        float4 x3 = *(const float4*)&xs[k][tg * 16 + 12];
        acc[0]  += wv * x0.x; acc[1]  += wv * x0.y; acc[2]  += wv * x0.z; acc[3]  += wv * x0.w;
        acc[4]  += wv * x1.x; acc[5]  += wv * x1.y; acc[6]  += wv * x1.z; acc[7]  += wv * x1.w;
        acc[8]  += wv * x2.x; acc[9]  += wv * x2.y; acc[10] += wv * x2.z; acc[11] += wv * x2.w;
        acc[12] += wv * x3.x; acc[13] += wv * x3.y; acc[14] += wv * x3.z; acc[15] += wv * x3.w;
    }

#pragma unroll
    for (int u = 0; u < 16; u++) {
        float v = acc[u]; int oo = o;
#pragma unroll
        for (int off = 16; off; off >>= 1) {
            float v2 = __shfl_xor_sync(0xffffffffu, v, off);
            int   o2 = __shfl_xor_sync(0xffffffffu, oo, off);
            if (v2 > v || (v2 == v && o2 < oo)) { v = v2; oo = o2; }
        }
        int te = tg * 16 + u;
        if ((tid & 31) == 0 && te < cnt) {
            u64 key = ((u64)enc_f(v) << 32) | (unsigned)(OD - 1 - oo);
            atomicMax(&g_best[toks[te] * NHEADS + h], key);
        }
    }
}

__global__ void decode_kernel() {
    const int h = blockIdx.x;
    unsigned n = g_r2n[h]; if (n > R2CAP) n = R2CAP;
    for (unsigned e = threadIdx.x; e < n; e += blockDim.x) {
        int pair = g_r2[h][e] * NHEADS + h;
        u64 key = g_best[pair];
        g_idx[pair] = (OD - 1) - (int)(key & 0xFFFFFFFFULL);
    }
}

// ---------------- gather ----------------
__global__ __launch_bounds__(256) void gather_kernel(const float* __restrict__ cb,
                                                     float* __restrict__ out) {
    const float4* cb4 = (const float4*)cb;
    float4* out4 = (float4*)out;
    int q = blockIdx.x * blockDim.x + threadIdx.x;
    int t = q >> 9, r = q & 511;
    int h = r >> 5, j = r & 31;
    int bi = g_idx[t * NHEADS + h];
    out4[(size_t)t * (EDIM / 4) + h * (KD / 4) + j] =
        cb4[((size_t)h * OD + bi) * (KD / 4) + j];
}

extern "C" void kernel_launch(void* const* d_in, const int* in_sizes, int n_in,
                              void* d_out, int out_size) {
    const float* x  = (const float*)d_in[0];
    const float* w  = (const float*)d_in[1];
    const float* cb = (const float*)d_in[2];
    // d_in[3] temperature: mathematically irrelevant in the forward pass.
    float* out = (float*)d_out;

    cudaFuncSetAttribute(vq_hybrid_kernel,
                         cudaFuncAttributeMaxDynamicSharedMemorySize, SM_TOT);

    prep_w_kernel<<<dim3(OD / 32, NHEADS), 256>>>(w);
    vq_hybrid_kernel<<<dim3(NTOK / TM, NHEADS), 256, SM_TOT>>>(x);
    rescue1_kernel<<<256, 256>>>(x, w);
    rescue2_kernel<<<dim3(NHEADS, 8, R2CAP / 32), 256>>>(x);
    decode_kernel<<<NHEADS, 256>>>();
    gather_kernel<<<(NTOK * EDIM / 4) / 256, 256>>>(cb, out);
}